// round 6
// baseline (speedup 1.0000x reference)
#include <cuda_runtime.h>
#include <math.h>
#include <stdint.h>

// Problem constants (fixed shapes)
#define NMAX 100000
#define EMAX 800000
#define DIM  64

// Scratch (__device__ globals: allocation-free rule)
__device__ float g_Q[NMAX * DIM];
__device__ float g_K[NMAX * DIM];
__device__ float g_V[NMAX * DIM];
__device__ float g_E[EMAX * DIM];
__device__ float g_Z[NMAX * 4];

// ---------------------------------------------------------------------------
// tf32 helpers
// ---------------------------------------------------------------------------
__device__ __forceinline__ uint32_t f2tf32(float x) {
    uint32_t r;
    asm("cvt.rna.tf32.f32 %0, %1;" : "=r"(r) : "f"(x));
    return r;
}

__device__ __forceinline__ void mma_tf32(float c[4], const uint32_t a[4],
                                         uint32_t b0, uint32_t b1) {
    asm volatile(
        "mma.sync.aligned.m16n8k8.row.col.f32.tf32.tf32.f32 "
        "{%0,%1,%2,%3}, {%4,%5,%6,%7}, {%8,%9}, {%0,%1,%2,%3};\n"
        : "+f"(c[0]), "+f"(c[1]), "+f"(c[2]), "+f"(c[3])
        : "r"(a[0]), "r"(a[1]), "r"(a[2]), "r"(a[3]), "r"(b0), "r"(b1));
}

// ---------------------------------------------------------------------------
// Kernel 1: zero wV accumulator (d_out) and Z
// ---------------------------------------------------------------------------
__global__ void init_kernel(float* __restrict__ out, int n) {
    int total = n * DIM;
    int zn = n * 4;
    for (int i = blockIdx.x * blockDim.x + threadIdx.x; i < total;
         i += gridDim.x * blockDim.x) {
        out[i] = 0.0f;
        if (i < zn) g_Z[i] = 0.0f;
    }
}

// ---------------------------------------------------------------------------
// Kernel 2: generic Y[M,64] = A[M,64] @ W[64,64].T via tf32 mma, 3-pass split
// (Ahi*Whi + Ahi*Wlo + Alo*Whi ~ fp32 accuracy).
// Block: 256 threads = 8 warps x 16 rows = 128 rows.
// W staged in smem transposed+split: sW[k*72 + o] (stride 72 -> conflict-free
// fragment loads: bank = 8*tig + gid, all 32 lanes distinct).
// sel: 0->g_Q, 1->g_K, 2->g_V, 3->g_E
// ---------------------------------------------------------------------------
__global__ __launch_bounds__(256) void gemm64_kernel(
    const float* __restrict__ A,
    const float* __restrict__ W,
    int M, int sel)
{
    __shared__ float sWhi[64 * 72];
    __shared__ float sWlo[64 * 72];
    for (int i = threadIdx.x; i < 64 * 64; i += 256) {
        int o = i >> 6, k = i & 63;
        float w = W[i];
        float hi = __uint_as_float(f2tf32(w));
        float lo = __uint_as_float(f2tf32(w - hi));
        sWhi[k * 72 + o] = hi;
        sWlo[k * 72 + o] = lo;
    }
    __syncthreads();

    int warp = threadIdx.x >> 5;
    int lane = threadIdx.x & 31;
    int gid = lane >> 2;       // 0..7
    int tig = lane & 3;        // 0..3

    int row0 = blockIdx.x * 128 + warp * 16 + gid;
    int row1 = row0 + 8;
    int r0 = min(row0, M - 1);
    int r1 = min(row1, M - 1);

    const float* A0 = A + (size_t)r0 * 64;
    const float* A1 = A + (size_t)r1 * 64;

    // A fragments: 8 k-steps x 4 regs, hi & lo
    uint32_t ahi[8][4], alo[8][4];
#pragma unroll
    for (int kk = 0; kk < 8; kk++) {
        float a0 = A0[kk * 8 + tig];
        float a1 = A1[kk * 8 + tig];
        float a2 = A0[kk * 8 + tig + 4];
        float a3 = A1[kk * 8 + tig + 4];
        ahi[kk][0] = f2tf32(a0);
        ahi[kk][1] = f2tf32(a1);
        ahi[kk][2] = f2tf32(a2);
        ahi[kk][3] = f2tf32(a3);
        alo[kk][0] = f2tf32(a0 - __uint_as_float(ahi[kk][0]));
        alo[kk][1] = f2tf32(a1 - __uint_as_float(ahi[kk][1]));
        alo[kk][2] = f2tf32(a2 - __uint_as_float(ahi[kk][2]));
        alo[kk][3] = f2tf32(a3 - __uint_as_float(ahi[kk][3]));
    }

    float* Y = (sel == 0) ? g_Q : (sel == 1) ? g_K : (sel == 2) ? g_V : g_E;

#pragma unroll
    for (int nn = 0; nn < 8; nn++) {
        float c[4] = {0.f, 0.f, 0.f, 0.f};
#pragma unroll
        for (int kk = 0; kk < 8; kk++) {
            int kb0 = (kk * 8 + tig) * 72 + nn * 8 + gid;
            int kb1 = (kk * 8 + tig + 4) * 72 + nn * 8 + gid;
            uint32_t bh0 = __float_as_uint(sWhi[kb0]);
            uint32_t bh1 = __float_as_uint(sWhi[kb1]);
            uint32_t bl0 = __float_as_uint(sWlo[kb0]);
            uint32_t bl1 = __float_as_uint(sWlo[kb1]);
            mma_tf32(c, ahi[kk], bh0, bh1);   // hi*hi
            mma_tf32(c, ahi[kk], bl0, bl1);   // hi*lo
            mma_tf32(c, alo[kk], bh0, bh1);   // lo*hi
        }
        int col = nn * 8 + 2 * tig;
        if (row0 < M)
            *(float2*)(Y + (size_t)row0 * 64 + col) = make_float2(c[0], c[1]);
        if (row1 < M)
            *(float2*)(Y + (size_t)row1 * 64 + col) = make_float2(c[2], c[3]);
    }
}

// ---------------------------------------------------------------------------
// Kernel 3: gather + score + exp + atomic scatter (no GEMM).
// 8 lanes per edge; lane 'sub' owns dims [8*sub, 8*sub+8). head = sub>>1.
// ---------------------------------------------------------------------------
__global__ __launch_bounds__(256) void scatter_kernel(
    const int* __restrict__ ei,     // [2, nE] int32
    float* __restrict__ out,        // [n, 64] accumulator
    int nE)
{
    int t = blockIdx.x * 256 + threadIdx.x;
    int e = t >> 3;
    int sub = t & 7;
    if (e >= nE) return;

    int s = __ldg(&ei[e]);
    int d = __ldg(&ei[nE + e]);

    const float4* E4 = (const float4*)g_E;
    const float4* Q4 = (const float4*)g_Q;
    const float4* K4 = (const float4*)g_K;
    const float4* V4 = (const float4*)g_V;

    int fe = e * 16 + 2 * sub;
    int fd = d * 16 + 2 * sub;
    int fs = s * 16 + 2 * sub;

    float4 e0 = E4[fe],     e1 = E4[fe + 1];
    float4 q0 = Q4[fd],     q1 = Q4[fd + 1];
    float4 k0 = K4[fs],     k1 = K4[fs + 1];

    float part = q0.x * k0.x * e0.x + q0.y * k0.y * e0.y
               + q0.z * k0.z * e0.z + q0.w * k0.w * e0.w
               + q1.x * k1.x * e1.x + q1.y * k1.y * e1.y
               + q1.z * k1.z * e1.z + q1.w * k1.w * e1.w;

    // head covers 16 dims = 2 adjacent lanes (sub pairs)
    float tsum = (part + __shfl_xor_sync(0xffffffffu, part, 1)) * 0.25f;
    float sc = __expf(fminf(fmaxf(tsum, -5.0f), 5.0f));

    float4 v0 = V4[fs], v1 = V4[fs + 1];
    float* ob = out + (size_t)d * 64 + 8 * sub;
    atomicAdd(ob + 0, v0.x * sc);
    atomicAdd(ob + 1, v0.y * sc);
    atomicAdd(ob + 2, v0.z * sc);
    atomicAdd(ob + 3, v0.w * sc);
    atomicAdd(ob + 4, v1.x * sc);
    atomicAdd(ob + 5, v1.y * sc);
    atomicAdd(ob + 6, v1.z * sc);
    atomicAdd(ob + 7, v1.w * sc);
    if ((sub & 1) == 0)
        atomicAdd(&g_Z[d * 4 + (sub >> 1)], sc);
}

// ---------------------------------------------------------------------------
// Kernel 4: out = wV / (Z + 1e-6), float4-vectorized
// ---------------------------------------------------------------------------
__global__ void fin_kernel(float* __restrict__ out, int n) {
    int total4 = n * 16;
    float4* o4 = (float4*)out;
    for (int i = blockIdx.x * blockDim.x + threadIdx.x; i < total4;
         i += gridDim.x * blockDim.x) {
        int node = i >> 4;
        int head = (i >> 2) & 3;
        float z = 1.0f / (g_Z[node * 4 + head] + 1e-6f);
        float4 v = o4[i];
        v.x *= z; v.y *= z; v.z *= z; v.w *= z;
        o4[i] = v;
    }
}

// ---------------------------------------------------------------------------
// Launch.  Inputs: x, edge_attr, Wq, Wk, We, Wv, edge_index (int32)
// ---------------------------------------------------------------------------
extern "C" void kernel_launch(void* const* d_in, const int* in_sizes, int n_in,
                              void* d_out, int out_size) {
    const float* x   = (const float*)d_in[0];
    const float* ea  = (const float*)d_in[1];
    const float* Wq  = (const float*)d_in[2];
    const float* Wk  = (const float*)d_in[3];
    const float* We  = (const float*)d_in[4];
    const float* Wv  = (const float*)d_in[5];
    const int*   ei  = (const int*)d_in[6];
    float* out = (float*)d_out;

    int n  = in_sizes[0] / DIM;   // 100000
    int nE = in_sizes[6] / 2;     // 800000

    init_kernel<<<2048, 256>>>(out, n);

    int nb_node = (n + 127) / 128;
    int nb_edge = (nE + 127) / 128;
    gemm64_kernel<<<nb_node, 256>>>(x,  Wq, n,  0);
    gemm64_kernel<<<nb_node, 256>>>(x,  Wk, n,  1);
    gemm64_kernel<<<nb_node, 256>>>(x,  Wv, n,  2);
    gemm64_kernel<<<nb_edge, 256>>>(ea, We, nE, 3);

    int nb_sc = (nE * 8 + 255) / 256;
    scatter_kernel<<<nb_sc, 256>>>(ei, out, nE);

    fin_kernel<<<2048, 256>>>(out, n);
}

// round 7
// speedup vs baseline: 1.0607x; 1.0607x over previous
#include <cuda_runtime.h>
#include <math.h>
#include <stdint.h>

// Problem constants (fixed shapes)
#define NMAX 100000
#define EMAX 800000
#define DIM  64

#define W_STRIDE 72
#define A_STRIDE 68

// Scratch (__device__ globals: allocation-free rule)
__device__ float g_Q[NMAX * DIM];
__device__ float g_K[NMAX * DIM];
__device__ float g_V[NMAX * DIM];
__device__ float g_E[EMAX * DIM];
__device__ float g_Z[NMAX * 4];

// ---------------------------------------------------------------------------
// tf32 helpers
// ---------------------------------------------------------------------------
__device__ __forceinline__ uint32_t f2tf32(float x) {
    uint32_t r;
    asm("cvt.rna.tf32.f32 %0, %1;" : "=r"(r) : "f"(x));
    return r;
}

__device__ __forceinline__ void mma_tf32(float c[4], const uint32_t a[4],
                                         uint32_t b0, uint32_t b1) {
    asm volatile(
        "mma.sync.aligned.m16n8k8.row.col.f32.tf32.tf32.f32 "
        "{%0,%1,%2,%3}, {%4,%5,%6,%7}, {%8,%9}, {%0,%1,%2,%3};\n"
        : "+f"(c[0]), "+f"(c[1]), "+f"(c[2]), "+f"(c[3])
        : "r"(a[0]), "r"(a[1]), "r"(a[2]), "r"(a[3]), "r"(b0), "r"(b1));
}

// ---------------------------------------------------------------------------
// Kernel 1: zero wV accumulator (d_out) and Z
// ---------------------------------------------------------------------------
__global__ void init_kernel(float* __restrict__ out, int n) {
    int total = n * DIM;
    int zn = n * 4;
    for (int i = blockIdx.x * blockDim.x + threadIdx.x; i < total;
         i += gridDim.x * blockDim.x) {
        out[i] = 0.0f;
        if (i < zn) g_Z[i] = 0.0f;
    }
}

// ---------------------------------------------------------------------------
// Kernel 2: multi-output tf32 GEMM, 3-pass split (Ahi*Whi+Ahi*Wlo+Alo*Whi).
// mode 0: Y={g_Q,g_K,g_V} from W0,W1,W2 (A staged once, reused 3x)
// mode 1: Y=g_E from W0
// Block: 256 thr = 8 warps x 16 rows = 128 rows of A.
// A staged coalesced (float4) into smem stride-68; fragments via LDS
// (banks 4*gid+tig: conflict-free). W transposed+split, stride-72.
// k-split (2 halves) keeps frag regs at 32; C accumulators persist (32 regs).
// ---------------------------------------------------------------------------
__global__ __launch_bounds__(256, 3) void gemm_multi(
    const float* __restrict__ A,
    const float* __restrict__ W0,
    const float* __restrict__ W1,
    const float* __restrict__ W2,
    int M, int mode)
{
    extern __shared__ float sm[];
    float* sWhi = sm;                       // 64*72
    float* sWlo = sm + 64 * W_STRIDE;       // 64*72
    float* sA   = sm + 2 * 64 * W_STRIDE;   // 128*68

    int tid = threadIdx.x;
    int base = blockIdx.x * 128;

    // Stage A: 128 rows x 16 float4, coalesced
    for (int i = tid; i < 128 * 16; i += 256) {
        int row = i >> 4, c4 = i & 15;
        int gr = min(base + row, M - 1);
        float4 v = ((const float4*)(A + (size_t)gr * 64))[c4];
        *(float4*)(sA + row * A_STRIDE + c4 * 4) = v;
    }

    int warp = tid >> 5, lane = tid & 31;
    int gid = lane >> 2, tig = lane & 3;
    int lrow0 = warp * 16 + gid;
    int lrow1 = lrow0 + 8;
    int grow0 = base + lrow0;
    int grow1 = base + lrow1;

    int nW = (mode == 0) ? 3 : 1;
    for (int w = 0; w < nW; w++) {
        const float* W = (w == 0) ? W0 : (w == 1) ? W1 : W2;

        __syncthreads();   // staging done (w=0) / previous compute done (w>0)
        for (int i = tid; i < 64 * 64; i += 256) {
            int o = i >> 6, k = i & 63;
            float wv = W[i];
            float hi = __uint_as_float(f2tf32(wv));
            sWhi[k * W_STRIDE + o] = hi;
            sWlo[k * W_STRIDE + o] = __uint_as_float(f2tf32(wv - hi));
        }
        __syncthreads();

        float c[8][4];
#pragma unroll
        for (int nn = 0; nn < 8; nn++)
#pragma unroll
            for (int i = 0; i < 4; i++) c[nn][i] = 0.0f;

#pragma unroll
        for (int kh = 0; kh < 2; kh++) {
            uint32_t ahi[4][4], alo[4][4];
#pragma unroll
            for (int kk = 0; kk < 4; kk++) {
                int k8 = (kh * 4 + kk) * 8;
                float a0 = sA[lrow0 * A_STRIDE + k8 + tig];
                float a1 = sA[lrow1 * A_STRIDE + k8 + tig];
                float a2 = sA[lrow0 * A_STRIDE + k8 + tig + 4];
                float a3 = sA[lrow1 * A_STRIDE + k8 + tig + 4];
                ahi[kk][0] = f2tf32(a0);
                ahi[kk][1] = f2tf32(a1);
                ahi[kk][2] = f2tf32(a2);
                ahi[kk][3] = f2tf32(a3);
                alo[kk][0] = f2tf32(a0 - __uint_as_float(ahi[kk][0]));
                alo[kk][1] = f2tf32(a1 - __uint_as_float(ahi[kk][1]));
                alo[kk][2] = f2tf32(a2 - __uint_as_float(ahi[kk][2]));
                alo[kk][3] = f2tf32(a3 - __uint_as_float(ahi[kk][3]));
            }
#pragma unroll
            for (int nn = 0; nn < 8; nn++) {
#pragma unroll
                for (int kk = 0; kk < 4; kk++) {
                    int krow = (kh * 4 + kk) * 8 + tig;
                    int kb0 = krow * W_STRIDE + nn * 8 + gid;
                    int kb1 = (krow + 4) * W_STRIDE + nn * 8 + gid;
                    uint32_t bh0 = __float_as_uint(sWhi[kb0]);
                    uint32_t bh1 = __float_as_uint(sWhi[kb1]);
                    uint32_t bl0 = __float_as_uint(sWlo[kb0]);
                    uint32_t bl1 = __float_as_uint(sWlo[kb1]);
                    mma_tf32(c[nn], ahi[kk], bh0, bh1);   // hi*hi
                    mma_tf32(c[nn], ahi[kk], bl0, bl1);   // hi*lo
                    mma_tf32(c[nn], alo[kk], bh0, bh1);   // lo*hi
                }
            }
        }

        float* Y = (mode == 1) ? g_E
                 : (w == 0) ? g_Q : (w == 1) ? g_K : g_V;
#pragma unroll
        for (int nn = 0; nn < 8; nn++) {
            int col = nn * 8 + 2 * tig;
            if (grow0 < M)
                *(float2*)(Y + (size_t)grow0 * 64 + col) = make_float2(c[nn][0], c[nn][1]);
            if (grow1 < M)
                *(float2*)(Y + (size_t)grow1 * 64 + col) = make_float2(c[nn][2], c[nn][3]);
        }
    }
}

// ---------------------------------------------------------------------------
// Kernel 3: gather + score + exp + atomic scatter.
// 8 lanes per edge; lane 'sub' owns dims [8*sub, 8*sub+8). head = sub>>1.
// ---------------------------------------------------------------------------
__global__ __launch_bounds__(256) void scatter_kernel(
    const int* __restrict__ ei,     // [2, nE] int32
    float* __restrict__ out,        // [n, 64] accumulator
    int nE)
{
    int t = blockIdx.x * 256 + threadIdx.x;
    int e = t >> 3;
    int sub = t & 7;
    if (e >= nE) return;

    int s = __ldg(&ei[e]);
    int d = __ldg(&ei[nE + e]);

    const float4* E4 = (const float4*)g_E;
    const float4* Q4 = (const float4*)g_Q;
    const float4* K4 = (const float4*)g_K;
    const float4* V4 = (const float4*)g_V;

    int fe = e * 16 + 2 * sub;
    int fd = d * 16 + 2 * sub;
    int fs = s * 16 + 2 * sub;

    float4 e0 = E4[fe],     e1 = E4[fe + 1];
    float4 q0 = Q4[fd],     q1 = Q4[fd + 1];
    float4 k0 = K4[fs],     k1 = K4[fs + 1];

    float part = q0.x * k0.x * e0.x + q0.y * k0.y * e0.y
               + q0.z * k0.z * e0.z + q0.w * k0.w * e0.w
               + q1.x * k1.x * e1.x + q1.y * k1.y * e1.y
               + q1.z * k1.z * e1.z + q1.w * k1.w * e1.w;

    float tsum = (part + __shfl_xor_sync(0xffffffffu, part, 1)) * 0.25f;
    float sc = __expf(fminf(fmaxf(tsum, -5.0f), 5.0f));

    float4 v0 = V4[fs], v1 = V4[fs + 1];
    float* ob = out + (size_t)d * 64 + 8 * sub;
    atomicAdd(ob + 0, v0.x * sc);
    atomicAdd(ob + 1, v0.y * sc);
    atomicAdd(ob + 2, v0.z * sc);
    atomicAdd(ob + 3, v0.w * sc);
    atomicAdd(ob + 4, v1.x * sc);
    atomicAdd(ob + 5, v1.y * sc);
    atomicAdd(ob + 6, v1.z * sc);
    atomicAdd(ob + 7, v1.w * sc);
    if ((sub & 1) == 0)
        atomicAdd(&g_Z[d * 4 + (sub >> 1)], sc);
}

// ---------------------------------------------------------------------------
// Kernel 4: out = wV / (Z + 1e-6), float4-vectorized
// ---------------------------------------------------------------------------
__global__ void fin_kernel(float* __restrict__ out, int n) {
    int total4 = n * 16;
    float4* o4 = (float4*)out;
    for (int i = blockIdx.x * blockDim.x + threadIdx.x; i < total4;
         i += gridDim.x * blockDim.x) {
        int node = i >> 4;
        int head = (i >> 2) & 3;
        float z = 1.0f / (g_Z[node * 4 + head] + 1e-6f);
        float4 v = o4[i];
        v.x *= z; v.y *= z; v.z *= z; v.w *= z;
        o4[i] = v;
    }
}

// ---------------------------------------------------------------------------
// Launch.  Inputs: x, edge_attr, Wq, Wk, We, Wv, edge_index (int32)
// ---------------------------------------------------------------------------
extern "C" void kernel_launch(void* const* d_in, const int* in_sizes, int n_in,
                              void* d_out, int out_size) {
    const float* x   = (const float*)d_in[0];
    const float* ea  = (const float*)d_in[1];
    const float* Wq  = (const float*)d_in[2];
    const float* Wk  = (const float*)d_in[3];
    const float* We  = (const float*)d_in[4];
    const float* Wv  = (const float*)d_in[5];
    const int*   ei  = (const int*)d_in[6];
    float* out = (float*)d_out;

    int n  = in_sizes[0] / DIM;   // 100000
    int nE = in_sizes[6] / 2;     // 800000

    const int SMEM = (2 * 64 * W_STRIDE + 128 * A_STRIDE) * 4;  // 71680 B
    static int smem_set = 0;
    if (!smem_set) {
        cudaFuncSetAttribute(gemm_multi,
                             cudaFuncAttributeMaxDynamicSharedMemorySize, SMEM);
        smem_set = 1;
    }

    init_kernel<<<2048, 256>>>(out, n);

    int nb_node = (n + 127) / 128;
    int nb_edge = (nE + 127) / 128;
    gemm_multi<<<nb_node, 256, SMEM>>>(x, Wq, Wk, Wv, n, 0);
    gemm_multi<<<nb_edge, 256, SMEM>>>(ea, We, We, We, nE, 1);

    int nb_sc = (nE * 8 + 255) / 256;
    scatter_kernel<<<nb_sc, 256>>>(ei, out, nE);

    fin_kernel<<<2048, 256>>>(out, n);
}

// round 8
// speedup vs baseline: 1.0807x; 1.0189x over previous
#include <cuda_runtime.h>
#include <math.h>
#include <stdint.h>

// Problem constants (fixed shapes)
#define NMAX 100000
#define EMAX 800000
#define DIM  64

#define W_STRIDE 72
#define A_STRIDE 68

// Scratch (__device__ globals: allocation-free rule)
__device__ float g_Q[NMAX * DIM];
__device__ float g_K[NMAX * DIM];
__device__ float g_V[NMAX * DIM];
__device__ float g_S[EMAX * 4];      // per-edge per-head exp(score)
__device__ int   g_cnt[NMAX];
__device__ int   g_off[NMAX + 1];
__device__ int   g_pos[NMAX];
__device__ int2  g_sorted[EMAX];     // (src, edge_id) grouped by dst

// ---------------------------------------------------------------------------
// tf32 helpers
// ---------------------------------------------------------------------------
__device__ __forceinline__ uint32_t f2tf32(float x) {
    uint32_t r;
    asm("cvt.rna.tf32.f32 %0, %1;" : "=r"(r) : "f"(x));
    return r;
}

__device__ __forceinline__ void mma_tf32(float c[4], const uint32_t a[4],
                                         uint32_t b0, uint32_t b1) {
    asm volatile(
        "mma.sync.aligned.m16n8k8.row.col.f32.tf32.tf32.f32 "
        "{%0,%1,%2,%3}, {%4,%5,%6,%7}, {%8,%9}, {%0,%1,%2,%3};\n"
        : "+f"(c[0]), "+f"(c[1]), "+f"(c[2]), "+f"(c[3])
        : "r"(a[0]), "r"(a[1]), "r"(a[2]), "r"(a[3]), "r"(b0), "r"(b1));
}

// ---------------------------------------------------------------------------
// CSR build: zero counts -> count per dst -> exclusive scan -> place
// ---------------------------------------------------------------------------
__global__ void zero_cnt_kernel(int n) {
    for (int i = blockIdx.x * blockDim.x + threadIdx.x; i < n;
         i += gridDim.x * blockDim.x)
        g_cnt[i] = 0;
}

__global__ void count_kernel(const int* __restrict__ ei, int nE) {
    for (int i = blockIdx.x * blockDim.x + threadIdx.x; i < nE;
         i += gridDim.x * blockDim.x)
        atomicAdd(&g_cnt[ei[nE + i]], 1);
}

// single block, 1024 threads: exclusive scan of g_cnt into g_off (+g_pos)
__global__ __launch_bounds__(1024) void scan_kernel(int n) {
    __shared__ int ssum[1024];
    int tid = threadIdx.x;
    int chunk = (n + 1023) / 1024;
    int start = tid * chunk;
    int stop = min(start + chunk, n);
    int s = 0;
    for (int i = start; i < stop; i++) s += g_cnt[i];
    ssum[tid] = s;
    __syncthreads();
    // inclusive scan over block
    for (int off = 1; off < 1024; off <<= 1) {
        int t = (tid >= off) ? ssum[tid - off] : 0;
        __syncthreads();
        ssum[tid] += t;
        __syncthreads();
    }
    int run = ssum[tid] - s;   // exclusive offset of this thread's chunk
    for (int i = start; i < stop; i++) {
        g_off[i] = run;
        g_pos[i] = run;
        run += g_cnt[i];
    }
    if (tid == 1023) g_off[n] = ssum[1023];
}

__global__ void place_kernel(const int* __restrict__ ei, int nE) {
    for (int e = blockIdx.x * blockDim.x + threadIdx.x; e < nE;
         e += gridDim.x * blockDim.x) {
        int d = ei[nE + e];
        int p = atomicAdd(&g_pos[d], 1);
        g_sorted[p] = make_int2(ei[e], e);
    }
}

// ---------------------------------------------------------------------------
// Multi-output tf32 GEMM, 3-pass split (Ahi*Whi+Ahi*Wlo+Alo*Whi).
// mode 0: Y={g_Q,g_K,g_V} from W0,W1,W2 (A staged once, reused 3x)
// mode 1: edge rows; Eproj kept in regs; epilogue computes per-head
//         exp(clip(sum(Eproj*Q[dst]*K[src])/4)) -> g_S[e*4+h]. No Eproj store.
// ---------------------------------------------------------------------------
__global__ __launch_bounds__(256, 3) void gemm_multi(
    const float* __restrict__ A,
    const float* __restrict__ W0,
    const float* __restrict__ W1,
    const float* __restrict__ W2,
    const int* __restrict__ ei,
    int M, int mode)
{
    extern __shared__ float sm[];
    float* sWhi = sm;                       // 64*72
    float* sWlo = sm + 64 * W_STRIDE;       // 64*72
    float* sA   = sm + 2 * 64 * W_STRIDE;   // 128*68

    int tid = threadIdx.x;
    int base = blockIdx.x * 128;

    // Stage A: 128 rows x 16 float4, coalesced
    for (int i = tid; i < 128 * 16; i += 256) {
        int row = i >> 4, c4 = i & 15;
        int gr = min(base + row, M - 1);
        float4 v = ((const float4*)(A + (size_t)gr * 64))[c4];
        *(float4*)(sA + row * A_STRIDE + c4 * 4) = v;
    }

    int warp = tid >> 5, lane = tid & 31;
    int gid = lane >> 2, tig = lane & 3;
    int lrow0 = warp * 16 + gid;
    int lrow1 = lrow0 + 8;
    int grow0 = base + lrow0;
    int grow1 = base + lrow1;

    int nW = (mode == 0) ? 3 : 1;
    for (int w = 0; w < nW; w++) {
        const float* W = (w == 0) ? W0 : (w == 1) ? W1 : W2;

        __syncthreads();
        for (int i = tid; i < 64 * 64; i += 256) {
            int o = i >> 6, k = i & 63;
            float wv = W[i];
            float hi = __uint_as_float(f2tf32(wv));
            sWhi[k * W_STRIDE + o] = hi;
            sWlo[k * W_STRIDE + o] = __uint_as_float(f2tf32(wv - hi));
        }
        __syncthreads();

        float c[8][4];
#pragma unroll
        for (int nn = 0; nn < 8; nn++)
#pragma unroll
            for (int i = 0; i < 4; i++) c[nn][i] = 0.0f;

#pragma unroll
        for (int kh = 0; kh < 2; kh++) {
            uint32_t ahi[4][4], alo[4][4];
#pragma unroll
            for (int kk = 0; kk < 4; kk++) {
                int k8 = (kh * 4 + kk) * 8;
                float a0 = sA[lrow0 * A_STRIDE + k8 + tig];
                float a1 = sA[lrow1 * A_STRIDE + k8 + tig];
                float a2 = sA[lrow0 * A_STRIDE + k8 + tig + 4];
                float a3 = sA[lrow1 * A_STRIDE + k8 + tig + 4];
                ahi[kk][0] = f2tf32(a0);
                ahi[kk][1] = f2tf32(a1);
                ahi[kk][2] = f2tf32(a2);
                ahi[kk][3] = f2tf32(a3);
                alo[kk][0] = f2tf32(a0 - __uint_as_float(ahi[kk][0]));
                alo[kk][1] = f2tf32(a1 - __uint_as_float(ahi[kk][1]));
                alo[kk][2] = f2tf32(a2 - __uint_as_float(ahi[kk][2]));
                alo[kk][3] = f2tf32(a3 - __uint_as_float(ahi[kk][3]));
            }
#pragma unroll
            for (int nn = 0; nn < 8; nn++) {
#pragma unroll
                for (int kk = 0; kk < 4; kk++) {
                    int krow = (kh * 4 + kk) * 8 + tig;
                    int kb0 = krow * W_STRIDE + nn * 8 + gid;
                    int kb1 = (krow + 4) * W_STRIDE + nn * 8 + gid;
                    uint32_t bh0 = __float_as_uint(sWhi[kb0]);
                    uint32_t bh1 = __float_as_uint(sWhi[kb1]);
                    uint32_t bl0 = __float_as_uint(sWlo[kb0]);
                    uint32_t bl1 = __float_as_uint(sWlo[kb1]);
                    mma_tf32(c[nn], ahi[kk], bh0, bh1);   // hi*hi
                    mma_tf32(c[nn], ahi[kk], bl0, bl1);   // hi*lo
                    mma_tf32(c[nn], alo[kk], bh0, bh1);   // lo*hi
                }
            }
        }

        if (mode == 0) {
            float* Y = (w == 0) ? g_Q : (w == 1) ? g_K : g_V;
#pragma unroll
            for (int nn = 0; nn < 8; nn++) {
                int col = nn * 8 + 2 * tig;
                if (grow0 < M)
                    *(float2*)(Y + (size_t)grow0 * 64 + col) = make_float2(c[nn][0], c[nn][1]);
                if (grow1 < M)
                    *(float2*)(Y + (size_t)grow1 * 64 + col) = make_float2(c[nn][2], c[nn][3]);
            }
        } else {
            // Score epilogue: row = edge id. Eproj values live in c[][].
            const float2* Q2 = (const float2*)g_Q;
            const float2* K2 = (const float2*)g_K;
#pragma unroll
            for (int r = 0; r < 2; r++) {
                int grow = (r == 0) ? grow0 : grow1;
                int e = min(grow, M - 1);
                int s = ei[e];
                int d = ei[M + e];
                float p[4] = {0.f, 0.f, 0.f, 0.f};
#pragma unroll
                for (int nn = 0; nn < 8; nn++) {
                    float2 q  = Q2[d * 32 + nn * 4 + tig];
                    float2 kk = K2[s * 32 + nn * 4 + tig];
                    float c0 = (r == 0) ? c[nn][0] : c[nn][2];
                    float c1 = (r == 0) ? c[nn][1] : c[nn][3];
                    p[nn >> 1] += c0 * q.x * kk.x + c1 * q.y * kk.y;
                }
#pragma unroll
                for (int h = 0; h < 4; h++) {
                    p[h] += __shfl_xor_sync(0xffffffffu, p[h], 1);
                    p[h] += __shfl_xor_sync(0xffffffffu, p[h], 2);
                }
                float sc = __expf(fminf(fmaxf(p[tig] * 0.25f, -5.0f), 5.0f));
                if (grow < M) g_S[e * 4 + tig] = sc;
            }
        }
    }
}

// ---------------------------------------------------------------------------
// Accumulation: one warp per dst node, no atomics. Lane l owns dims 2l,2l+1;
// head = l>>3. out = sum(V[src]*sc) / (sum(sc)+1e-6), written once.
// ---------------------------------------------------------------------------
__global__ __launch_bounds__(256) void accum_kernel(float* __restrict__ out, int n) {
    int warp = threadIdx.x >> 5, l = threadIdx.x & 31;
    int node = blockIdx.x * 8 + warp;
    if (node >= n) return;

    int beg = g_off[node], end = g_off[node + 1];
    int head = l >> 3;
    const float2* V2 = (const float2*)g_V;

    float2 acc = make_float2(0.f, 0.f);
    float z = 0.f;
    for (int j = beg; j < end; j++) {
        int2 se = g_sorted[j];
        float sc = g_S[se.y * 4 + head];
        float2 v = V2[se.x * 32 + l];
        acc.x += v.x * sc;
        acc.y += v.y * sc;
        z += sc;
    }
    float inv = 1.0f / (z + 1e-6f);
    ((float2*)out)[node * 32 + l] = make_float2(acc.x * inv, acc.y * inv);
}

// ---------------------------------------------------------------------------
// Launch.  Inputs: x, edge_attr, Wq, Wk, We, Wv, edge_index (int32)
// ---------------------------------------------------------------------------
extern "C" void kernel_launch(void* const* d_in, const int* in_sizes, int n_in,
                              void* d_out, int out_size) {
    const float* x   = (const float*)d_in[0];
    const float* ea  = (const float*)d_in[1];
    const float* Wq  = (const float*)d_in[2];
    const float* Wk  = (const float*)d_in[3];
    const float* We  = (const float*)d_in[4];
    const float* Wv  = (const float*)d_in[5];
    const int*   ei  = (const int*)d_in[6];
    float* out = (float*)d_out;

    int n  = in_sizes[0] / DIM;   // 100000
    int nE = in_sizes[6] / 2;     // 800000

    const int SMEM = (2 * 64 * W_STRIDE + 128 * A_STRIDE) * 4;  // 71680 B
    static int smem_set = 0;
    if (!smem_set) {
        cudaFuncSetAttribute(gemm_multi,
                             cudaFuncAttributeMaxDynamicSharedMemorySize, SMEM);
        smem_set = 1;
    }

    // CSR build
    zero_cnt_kernel<<<256, 256>>>(n);
    count_kernel<<<1024, 256>>>(ei, nE);
    scan_kernel<<<1, 1024>>>(n);
    place_kernel<<<1024, 256>>>(ei, nE);

    // Projections
    int nb_node = (n + 127) / 128;
    int nb_edge = (nE + 127) / 128;
    gemm_multi<<<nb_node, 256, SMEM>>>(x, Wq, Wk, Wv, nullptr, n, 0);
    gemm_multi<<<nb_edge, 256, SMEM>>>(ea, We, We, We, ei, nE, 1);

    // Per-node accumulation (no atomics) + normalization
    accum_kernel<<<(n + 7) / 8, 256>>>(out, n);
}